// round 7
// baseline (speedup 1.0000x reference)
#include <cuda_runtime.h>

#define THR 0.5f
#define MIN_JUMP_ENERGY 0.5f
#define MIN_VELOCITY_THRESHOLD 0.1f
#define MIN_WALL_JUMP_SPEED 1.0f

static constexpr int B = 32;
static constexpr int E = 100000;   // divisible by 32 (not 64): sub-tiles are warp-uniform

__device__ __forceinline__ unsigned edge_disable(
    float4 c0, float4 c1, float4 c2, float4 c3,
    float vel, float wall, float ke, float cj, float cwj)
{
    // argmax over cols 0..5, first-max-wins (strict >)
    int   et = 0;
    float mx = c0.x;
    if (c0.y > mx) { mx = c0.y; et = 1; }
    if (c0.z > mx) { mx = c0.z; et = 2; }
    if (c0.w > mx) { mx = c0.w; et = 3; }
    if (c1.x > mx) { mx = c1.x; et = 4; }
    if (c1.y > mx) { mx = c1.y; et = 5; }

    const float energy_cost           = c2.z;  // col 10
    const float min_velocity          = c3.x;  // col 12
    const float max_velocity          = c3.y;  // col 13
    const float requires_jump         = c3.z;  // col 14
    const float requires_wall_contact = c3.w;  // col 15

    // jnp.select: first-true-wins priority chain
    const bool cc1 = (et == 1) && (cj < THR);
    const bool cc2 = (et == 3);
    const bool d2  = (wall < THR) || (vel < MIN_VELOCITY_THRESHOLD);
    const bool cc3 = (requires_jump > THR);
    const bool d3  = (cj < THR) || (vel < min_velocity);
    const bool cc4 = (requires_wall_contact > THR);
    const bool d4  = (wall < THR) ||
                     ((cwj < THR) && (vel < MIN_WALL_JUMP_SPEED));
    const bool cc5 = (et == 1);
    const bool d5  = (ke < energy_cost * MIN_JUMP_ENERGY);

    bool dis;
    if      (cc1) dis = true;
    else if (cc2) dis = d2;
    else if (cc3) dis = d3;
    else if (cc4) dis = d4;
    else if (cc5) dis = d5;
    else          dis = false;

    const bool over  = (max_velocity > 0.0f) && (vel > max_velocity);
    const bool under = (!over) && (vel < min_velocity);
    return (dis || over || under) ? 1u : 0u;
}

__global__ __launch_bounds__(256) void edge_mask_kernel(
    const float4* __restrict__ feat,     // [B, E, 16] as float4[B*E*4]
    const float*  __restrict__ phys,     // [B, 18]
    const float*  __restrict__ base,     // [B, E]
    float*        __restrict__ out)      // [B, E]
{
    __shared__ float4 sh[8][128];        // 2 KB per warp (reused across both sub-tiles)

    const int b    = blockIdx.y;
    const int warp = threadIdx.x >> 5;
    const int lane = threadIdx.x & 31;
    const int rowA = blockIdx.x * 512 + warp * 64;   // first 32-row sub-tile
    if (rowA >= E) return;                           // warp-uniform
    const int  rowB    = rowA + 32;                  // second sub-tile
    const bool haveB   = (rowB < E);                 // warp-uniform (E % 32 == 0)

    // Per-batch physics scalars (uniform, cached)
    const float* p = phys + b * 18;
    const float vel  = p[2];
    const float wall = p[5];
    const float ke   = p[9];
    const float cj   = p[16];
    const float cwj  = p[17];

    const size_t  bOff = (size_t)b * E;
    const float4* fA   = feat + (bOff + (size_t)rowA) * 4;

    // ── Front-batched streaming loads: MLP_p1 = 10 ───────────────────────
    const float bvalA = __ldcs(base + bOff + rowA + lane);
    float bvalB = 0.0f;
    if (haveB) bvalB = __ldcs(base + bOff + rowB + lane);

    float4 a0 = __ldcs(fA +   0 + lane);
    float4 a1 = __ldcs(fA +  32 + lane);
    float4 a2 = __ldcs(fA +  64 + lane);
    float4 a3 = __ldcs(fA +  96 + lane);
    float4 b0, b1, b2, b3;
    if (haveB) {
        b0 = __ldcs(fA + 128 + lane);
        b1 = __ldcs(fA + 160 + lane);
        b2 = __ldcs(fA + 192 + lane);
        b3 = __ldcs(fA + 224 + lane);
    }

    float4* s = sh[warp];
    const int i0 = 0 * 32 + lane, i1 = 1 * 32 + lane,
              i2 = 2 * 32 + lane, i3 = 3 * 32 + lane;
    const int j0 = lane * 4 + 0, j1 = lane * 4 + 1,
              j2 = lane * 4 + 2, j3 = lane * 4 + 3;
    const int w0 = i0 ^ ((i0 >> 2) & 7), w1 = i1 ^ ((i1 >> 2) & 7),
              w2 = i2 ^ ((i2 >> 2) & 7), w3 = i3 ^ ((i3 >> 2) & 7);
    const int r0 = j0 ^ ((j0 >> 2) & 7), r1 = j1 ^ ((j1 >> 2) & 7),
              r2 = j2 ^ ((j2 >> 2) & 7), r3 = j3 ^ ((j3 >> 2) & 7);

    // ── Pass A: transpose + compute + store ──────────────────────────────
    s[w0] = a0; s[w1] = a1; s[w2] = a2; s[w3] = a3;
    __syncwarp();
    {
        const float4 c0 = s[r0], c1 = s[r1], c2 = s[r2], c3 = s[r3];
        const unsigned dis = edge_disable(c0, c1, c2, c3, vel, wall, ke, cj, cwj);
        __stcs(out + bOff + rowA + lane, dis ? 0.0f : bvalA);
    }

    // ── Pass B ───────────────────────────────────────────────────────────
    if (haveB) {
        __syncwarp();
        s[w0] = b0; s[w1] = b1; s[w2] = b2; s[w3] = b3;
        __syncwarp();
        const float4 c0 = s[r0], c1 = s[r1], c2 = s[r2], c3 = s[r3];
        const unsigned dis = edge_disable(c0, c1, c2, c3, vel, wall, ke, cj, cwj);
        __stcs(out + bOff + rowB + lane, dis ? 0.0f : bvalB);
    }
}

extern "C" void kernel_launch(void* const* d_in, const int* in_sizes, int n_in,
                              void* d_out, int out_size)
{
    const float4* feat = (const float4*)d_in[0];
    const float*  phys = (const float*) d_in[1];
    const float*  base = (const float*) d_in[2];
    float*        out  = (float*)d_out;

    dim3 block(256);
    dim3 grid((E + 511) / 512, B);   // 196 x 32 = 6272 CTAs
    edge_mask_kernel<<<grid, block>>>(feat, phys, base, out);
}

// round 8
// speedup vs baseline: 1.0617x; 1.0617x over previous
#include <cuda_runtime.h>

#define THR 0.5f
#define MIN_JUMP_ENERGY 0.5f
#define MIN_VELOCITY_THRESHOLD 0.1f
#define MIN_WALL_JUMP_SPEED 1.0f

static constexpr int B = 32;
static constexpr int E = 100000;

__global__ __launch_bounds__(256) void edge_mask_kernel(
    const float4* __restrict__ feat,     // [B, E, 16] viewed as float4[B*E*4]
    const float*  __restrict__ phys,     // [B, 18]
    const float*  __restrict__ base,     // [B, E]
    float*        __restrict__ out)      // [B, E]
{
    const int b = blockIdx.y;
    const int e = blockIdx.x * blockDim.x + threadIdx.x;
    if (e >= E) return;

    const size_t row = (size_t)b * E + e;
    const float4* f = feat + row * 4;

    // Front-batched streaming loads (MLP_p1 = 5)
    const float4 f0 = __ldcs(f + 0);   // cols 0-3
    const float4 f1 = __ldcs(f + 1);   // cols 4-7
    const float4 f2 = __ldcs(f + 2);   // cols 8-11
    const float4 f3 = __ldcs(f + 3);   // cols 12-15
    const float  bval = __ldcs(base + row);

    // Per-batch physics scalars (warp-uniform; cached)
    const float* p = phys + b * 18;
    const float vel  = p[2];
    const float wall = p[5];
    const float ke   = p[9];
    const float cj   = p[16];
    const float cwj  = p[17];

    // argmax over cols 0..5, first-max-wins (strict >)
    int   et = 0;
    float mx = f0.x;
    if (f0.y > mx) { mx = f0.y; et = 1; }
    if (f0.z > mx) { mx = f0.z; et = 2; }
    if (f0.w > mx) { mx = f0.w; et = 3; }
    if (f1.x > mx) { mx = f1.x; et = 4; }
    if (f1.y > mx) { mx = f1.y; et = 5; }

    const float energy_cost           = f2.z;  // col 10
    const float min_velocity          = f3.x;  // col 12
    const float max_velocity          = f3.y;  // col 13
    const float requires_jump         = f3.z;  // col 14
    const float requires_wall_contact = f3.w;  // col 15

    // jnp.select: first-true-wins priority chain
    const bool cc1 = (et == 1) && (cj < THR);
    const bool cc2 = (et == 3);
    const bool d2  = (wall < THR) || (vel < MIN_VELOCITY_THRESHOLD);
    const bool cc3 = (requires_jump > THR);
    const bool d3  = (cj < THR) || (vel < min_velocity);
    const bool cc4 = (requires_wall_contact > THR);
    const bool d4  = (wall < THR) ||
                     ((cwj < THR) && (vel < MIN_WALL_JUMP_SPEED));
    const bool cc5 = (et == 1);
    const bool d5  = (ke < energy_cost * MIN_JUMP_ENERGY);

    bool dis;
    if      (cc1) dis = true;
    else if (cc2) dis = d2;
    else if (cc3) dis = d3;
    else if (cc4) dis = d4;
    else if (cc5) dis = d5;
    else          dis = false;

    const bool over  = (max_velocity > 0.0f) && (vel > max_velocity);
    const bool under = (!over) && (vel < min_velocity);
    dis = dis || over || under;

    __stcs(out + row, dis ? 0.0f : bval);
}

extern "C" void kernel_launch(void* const* d_in, const int* in_sizes, int n_in,
                              void* d_out, int out_size)
{
    const float4* feat = (const float4*)d_in[0];
    const float*  phys = (const float*) d_in[1];
    const float*  base = (const float*) d_in[2];
    float*        out  = (float*)d_out;

    dim3 block(256);
    dim3 grid((E + 255) / 256, B);
    edge_mask_kernel<<<grid, block>>>(feat, phys, base, out);
}